// round 14
// baseline (speedup 1.0000x reference)
#include <cuda_runtime.h>
#include <cuda_fp16.h>
#include <cuda_bf16.h>
#include <stdint.h>

// Problem constants
#define OUTF   11008
#define INF    4096
#define MTOT   512
#define NUM_GROUPS 1409024               // OUTF*INF/32

#define N_TILE 128
#define M_TILE 128
#define KCHUNK 64
#define KSPLIT 4
#define NCHUNK_JOB (INF / KCHUNK / KSPLIT)   // 16 chunks per job
#define NTHREADS 256                     // 8 warps, warp tile m64 x n32

// XOR-swizzled layout: 128B rows, physical 16B-unit = col ^ (row & 7)
#define PITCH 128
#define STAGE_BYTES (128 * PITCH)        // 16384 per tile (A or B)
// A: 3 stages + B: 3 stages
#define SMEM_BYTES (6 * STAGE_BYTES)     // 98304 -> 2 CTAs/SM

// element counts for input identification (all distinct)
#define N_X   (MTOT * INF)               // 2,097,152 fp32
#define N_WQ  (NUM_GROUPS * 12)          // 16,908,288 int32
#define N_WN  NUM_GROUPS                 // 1,409,024 (dtype auto-detected)
#define N_B   OUTF                       // 11,008 fp32

// fused prep partition (512 threads per block)
#define NB_DQ  (NUM_GROUPS / 512)        // 2752  (dequant: 1 group/thread)
#define NB_X   (MTOT * INF / 2 / 512)    // 2048  (x convert: 1 half2/thread)
#define NB_OUT (MTOT * OUTF / 4 / 512)   // 2752  (out init: 1 float4/thread)

__device__ __align__(16) __half g_xh[MTOT * INF];     // fp16 activations (4 MB)
__device__ __align__(16) __half g_w[(size_t)OUTF * INF];  // dequantized weights (90 MB)

// ---------------- helpers ----------------
__device__ __forceinline__ uint32_t smem_u32(const void* p) {
    uint32_t a;
    asm("{ .reg .u64 t; cvta.to.shared.u64 t, %1; cvt.u32.u64 %0, t; }" : "=r"(a) : "l"(p));
    return a;
}

__device__ __forceinline__ void cpasync16(uint32_t dst, const void* src) {
    asm volatile("cp.async.cg.shared.global [%0], [%1], 16;" :: "r"(dst), "l"(src) : "memory");
}

__device__ __forceinline__ void ldm_x4(uint32_t* r, uint32_t addr) {
    asm volatile("ldmatrix.sync.aligned.m8n8.x4.shared.b16 {%0,%1,%2,%3}, [%4];"
                 : "=r"(r[0]), "=r"(r[1]), "=r"(r[2]), "=r"(r[3]) : "r"(addr));
}

__device__ __forceinline__ void mma16816(float* c, const uint32_t* a, const uint32_t b0, const uint32_t b1) {
    asm volatile(
        "mma.sync.aligned.m16n8k16.row.col.f32.f16.f16.f32 "
        "{%0,%1,%2,%3}, {%4,%5,%6,%7}, {%8,%9}, {%0,%1,%2,%3};"
        : "+f"(c[0]), "+f"(c[1]), "+f"(c[2]), "+f"(c[3])
        : "r"(a[0]), "r"(a[1]), "r"(a[2]), "r"(a[3]), "r"(b0), "r"(b1));
}

// Decode 8 3-bit codes from 3 bytes (each held in an int32), dequantize, pack to 4x half2.
__device__ __forceinline__ uint4 dec8(int b0, int b1, int b2, float a, float nb) {
    float w0 = fmaf((float)(b0 & 7), a, nb);
    float w1 = fmaf((float)((b0 >> 3) & 7), a, nb);
    float w2 = fmaf((float)(((b0 >> 6) & 3) | ((b1 & 1) << 2)), a, nb);
    float w3 = fmaf((float)((b1 >> 1) & 7), a, nb);
    float w4 = fmaf((float)((b1 >> 4) & 7), a, nb);
    float w5 = fmaf((float)(((b1 >> 7) & 1) | ((b2 & 3) << 1)), a, nb);
    float w6 = fmaf((float)((b2 >> 2) & 7), a, nb);
    float w7 = fmaf((float)((b2 >> 5) & 7), a, nb);
    uint4 u;
    asm("cvt.rn.f16x2.f32 %0, %1, %2;" : "=r"(u.x) : "f"(w1), "f"(w0));
    asm("cvt.rn.f16x2.f32 %0, %1, %2;" : "=r"(u.y) : "f"(w3), "f"(w2));
    asm("cvt.rn.f16x2.f32 %0, %1, %2;" : "=r"(u.z) : "f"(w5), "f"(w4));
    asm("cvt.rn.f16x2.f32 %0, %1, %2;" : "=r"(u.w) : "f"(w7), "f"(w6));
    return u;
}

// ---------------- fused prep: W dequant (with local wn-dtype vote), x convert, out init ----
// Norms lie in (0.01, 0.11); dequant blocks re-vote dtype locally over wn[0..255].
__global__ void __launch_bounds__(512) prep_kernel(
    const void* __restrict__ wn, const int* __restrict__ wq,
    const float* __restrict__ x, const float* __restrict__ bias,
    float* __restrict__ out)
{
    int b = blockIdx.x;
    if (b < NB_DQ) {
        __shared__ int votes[3];
        if (threadIdx.x < 3) votes[threadIdx.x] = 0;
        __syncthreads();
        {
            int j = threadIdx.x & 255;
            float a = ((const float*)wn)[j];
            float h = __half2float(((const __half*)wn)[j]);
            float c = __bfloat162float(((const __nv_bfloat16*)wn)[j]);
            if (a > 0.009f && a < 0.115f) atomicAdd(&votes[0], 1);
            if (h > 0.009f && h < 0.115f) atomicAdd(&votes[1], 1);
            if (c > 0.009f && c < 0.115f) atomicAdd(&votes[2], 1);
        }
        __syncthreads();
        int mode = 1, best = votes[1];
        if (votes[0] > best) { best = votes[0]; mode = 0; }
        if (votes[2] > best) { best = votes[2]; mode = 2; }

        int g = b * 512 + threadIdx.x;               // group index (contiguous in k)
        float n;
        if (mode == 0)      n = ((const float*)wn)[g];
        else if (mode == 1) n = __half2float(((const __half*)wn)[g]);
        else                n = __bfloat162float(((const __nv_bfloat16*)wn)[g]);
        const int4* pk = (const int4*)wq + (size_t)g * 3;
        int4 w0 = __ldg(pk), w1 = __ldg(pk + 1), w2 = __ldg(pk + 2);
        float aa = n * (2.0f / 7.0f), nb = -n;
        uint4* dst = (uint4*)(g_w + (size_t)g * 32);  // 32 halves = 4 x uint4
        dst[0] = dec8(w0.x, w0.y, w0.z, aa, nb);
        dst[1] = dec8(w0.w, w1.x, w1.y, aa, nb);
        dst[2] = dec8(w1.z, w1.w, w2.x, aa, nb);
        dst[3] = dec8(w2.y, w2.z, w2.w, aa, nb);
    } else if (b < NB_DQ + NB_X) {
        int i = (b - NB_DQ) * 512 + threadIdx.x;
        float2 v = ((const float2*)x)[i];
        ((__half2*)g_xh)[i] = __floats2half2_rn(v.x, v.y);
    } else {
        int i = (b - NB_DQ - NB_X) * 512 + threadIdx.x;     // float4 index
        int n4 = (i % (OUTF / 4)) * 4;
        float4 bb = *(const float4*)(bias + n4);
        ((float4*)out)[i] = bb;
    }
}

// ---------------- pure fp16 GEMM, split-K, 8 warps @ m64n32, 3-stage A+B cp.async,
// ---------------- XOR-swizzled smem + cross-chunk fragment prefetch ----------------
__global__ void __launch_bounds__(NTHREADS, 2) l3b_gemm(float* __restrict__ out)
{
    extern __shared__ char smem[];
    const uint32_t sb = smem_u32(smem);
    const int tid = threadIdx.x;
    const int wid = tid >> 5, lid = tid & 31;
    const int wm = wid >> 2, wn_ = wid & 3;          // 2x4 warp grid, warp tile m64 x n32
    const int m0 = blockIdx.x * M_TILE;              // m fast-varying: L2 weight reuse
    const int n0 = blockIdx.y * N_TILE;
    const int c0 = blockIdx.z * NCHUNK_JOB;          // split-K chunk base

    const uint32_t As0 = sb;                         // 3 A stages
    const uint32_t Bs0 = sb + 3 * STAGE_BYTES;       // 3 B stages

    // cp.async per-thread mapping with XOR swizzle (phys unit = col ^ (row & 7))
    const int ld_row = tid >> 3, ld_col = tid & 7;   // base row 0..31 (step 32 per p), col 0..7
    const uint32_t ld_soff = (uint32_t)(ld_row * PITCH + ((ld_col ^ (ld_row & 7)) * 16));
    const __half* ag = g_xh + (size_t)(m0 + ld_row) * INF + ld_col * 8;
    const __half* bg = g_w  + (size_t)(n0 + ld_row) * INF + ld_col * 8;

    // ldmatrix lane addressing (swizzled): addr = base_row*128 + ((2*ks + hi) ^ r7)*16
    const uint32_t a_base = (uint32_t)((wm * 64 + (lid & 15)) * PITCH);
    const uint32_t a_hi = (uint32_t)(lid >> 4);
    const uint32_t b_base = (uint32_t)((wn_ * 32 + ((lid >> 4) << 3) + (lid & 7)) * PITCH);
    const uint32_t b_hi = (uint32_t)((lid >> 3) & 1);
    const uint32_t r7 = (uint32_t)(lid & 7);

    float acc[4][4][4];
    #pragma unroll
    for (int mt = 0; mt < 4; mt++)
        #pragma unroll
        for (int nt = 0; nt < 4; nt++)
            #pragma unroll
            for (int e = 0; e < 4; e++) acc[mt][nt][e] = 0.0f;

    // ---- prologue: stage chunks c0 -> stage0, c0+1 -> stage1 (A and B per group) ----
    #pragma unroll
    for (int s = 0; s < 2; s++) {
        const uint32_t As = As0 + (uint32_t)s * STAGE_BYTES;
        const uint32_t Bs = Bs0 + (uint32_t)s * STAGE_BYTES;
        const int koff = (c0 + s) * KCHUNK;
        #pragma unroll
        for (int p = 0; p < 4; p++) {
            cpasync16(As + ld_soff + (uint32_t)(p * 32 * PITCH), ag + (size_t)(p * 32) * INF + koff);
            cpasync16(Bs + ld_soff + (uint32_t)(p * 32 * PITCH), bg + (size_t)(p * 32) * INF + koff);
        }
        asm volatile("cp.async.commit_group;" ::: "memory");
    }
    asm volatile("cp.async.wait_group 1;" ::: "memory");   // chunk c0 landed
    __syncthreads();

    uint32_t af[2][4][4], bf[2][4];
    // preload chunk 0, k-step 0 A fragments
    #pragma unroll
    for (int mt = 0; mt < 4; mt++)
        ldm_x4(af[0][mt], As0 + a_base + (uint32_t)(mt * 16 * PITCH) + ((a_hi ^ r7) << 4));

    int rd3 = 0;                                     // read stage (i % 3)

    #pragma unroll 1
    for (int i = 0; i < NCHUNK_JOB; i++) {
        const uint32_t As = As0 + (uint32_t)rd3 * STAGE_BYTES;
        const uint32_t Bs = Bs0 + (uint32_t)rd3 * STAGE_BYTES;

        const bool more = (i + 1 < NCHUNK_JOB);
        const bool more2 = (i + 2 < NCHUNK_JOB);

        // ---- B fragments for k-step 0 of this chunk ----
        #pragma unroll
        for (int nt2 = 0; nt2 < 2; nt2++)
            ldm_x4(bf[nt2], Bs + b_base + (uint32_t)(nt2 * 16 * PITCH) + ((b_hi ^ r7) << 4));

        // ---- issue chunk i+2 cp.async into stage (rd3+2)%3 ----
        if (more2) {
            int wr3 = rd3 + 2; if (wr3 >= 3) wr3 -= 3;
            const uint32_t Aw = As0 + (uint32_t)wr3 * STAGE_BYTES;
            const uint32_t Bw = Bs0 + (uint32_t)wr3 * STAGE_BYTES;
            const int koff = (c0 + i + 2) * KCHUNK;
            #pragma unroll
            for (int p = 0; p < 4; p++) {
                cpasync16(Aw + ld_soff + (uint32_t)(p * 32 * PITCH), ag + (size_t)(p * 32) * INF + koff);
                cpasync16(Bw + ld_soff + (uint32_t)(p * 32 * PITCH), bg + (size_t)(p * 32) * INF + koff);
            }
            asm volatile("cp.async.commit_group;" ::: "memory");
        }

        // ---- compute chunk i: 4 k16 steps; af double-buffered; cross-chunk prefetch at ks3 ----
        #pragma unroll
        for (int ks = 0; ks < 4; ks++) {
            const int cur = ks & 1;
            if (ks < 3) {
                // prefetch A fragments of k-step ks+1 (overlaps with MMAs below)
                const uint32_t ux = (uint32_t)(((ks + 1) * 2 + a_hi) ^ r7) << 4;
                #pragma unroll
                for (int mt = 0; mt < 4; mt++)
                    ldm_x4(af[cur ^ 1][mt], As + a_base + (uint32_t)(mt * 16 * PITCH) + ux);
            } else if (more) {
                // chunk i+1 guaranteed in flight; wait for it, then preload its ks0 A
                // fragments into af[0] (free at ks==3) so post-barrier MMAs start instantly.
                if (more2) { asm volatile("cp.async.wait_group 1;" ::: "memory"); }
                else       { asm volatile("cp.async.wait_group 0;" ::: "memory"); }
                int rdn = rd3 + 1; if (rdn >= 3) rdn -= 3;
                const uint32_t An = As0 + (uint32_t)rdn * STAGE_BYTES;
                const uint32_t ux = (a_hi ^ r7) << 4;
                #pragma unroll
                for (int mt = 0; mt < 4; mt++)
                    ldm_x4(af[0][mt], An + a_base + (uint32_t)(mt * 16 * PITCH) + ux);
            }
            // 16 MMAs of k-step ks
            #pragma unroll
            for (int mt = 0; mt < 4; mt++)
                #pragma unroll
                for (int nt = 0; nt < 4; nt++)
                    mma16816(acc[mt][nt], af[cur][mt],
                             bf[nt >> 1][(nt & 1) * 2], bf[nt >> 1][(nt & 1) * 2 + 1]);
            // B fragments of k-step ks+1 (after last use of bf)
            if (ks < 3) {
                const uint32_t ux = (uint32_t)(((ks + 1) * 2 + b_hi) ^ r7) << 4;
                #pragma unroll
                for (int nt2 = 0; nt2 < 2; nt2++)
                    ldm_x4(bf[nt2], Bs + b_base + (uint32_t)(nt2 * 16 * PITCH) + ux);
            }
        }

        // ---- stage-rotation barrier (stage rd3+2 gets overwritten next chunk) ----
        if (more) __syncthreads();

        rd3++; if (rd3 == 3) rd3 = 0;
    }

    // ---- epilogue: atomic accumulate split-K partials (bias pre-broadcast by prep) ----
    #pragma unroll
    for (int mt = 0; mt < 4; mt++) {
        #pragma unroll
        for (int nt = 0; nt < 4; nt++) {
            int m = m0 + wm * 64 + mt * 16 + (lid >> 2);
            int nl = n0 + wn_ * 32 + nt * 8 + (lid & 3) * 2;
            float* p0 = out + (size_t)m * OUTF + nl;
            float* p1 = out + (size_t)(m + 8) * OUTF + nl;
            atomicAdd(p0,     acc[mt][nt][0]);
            atomicAdd(p0 + 1, acc[mt][nt][1]);
            atomicAdd(p1,     acc[mt][nt][2]);
            atomicAdd(p1 + 1, acc[mt][nt][3]);
        }
    }
}

// ---------------- launch ----------------
extern "C" void kernel_launch(void* const* d_in, const int* in_sizes, int n_in,
                              void* d_out, int out_size) {
    // Bind inputs by element count (robust to metadata ordering).
    const float* x    = 0;
    const int*   wq   = 0;
    const void*  wn   = 0;
    const float* bias = 0;
    for (int i = 0; i < n_in; i++) {
        switch (in_sizes[i]) {
            case N_X:  x    = (const float*)d_in[i]; break;
            case N_WQ: wq   = (const int*)d_in[i];   break;
            case N_WN: wn   = d_in[i];               break;
            case N_B:  bias = (const float*)d_in[i]; break;
            default: break;
        }
    }
    if (!x)    x    = (const float*)d_in[0];
    if (!wq)   wq   = (const int*)d_in[1];
    if (!wn)   wn   = d_in[2];
    if (!bias) bias = (const float*)d_in[3];

    float* out = (float*)d_out;

    cudaFuncSetAttribute(l3b_gemm, cudaFuncAttributeMaxDynamicSharedMemorySize, SMEM_BYTES);

    prep_kernel<<<NB_DQ + NB_X + NB_OUT, 512>>>(wn, wq, x, bias, out);

    dim3 grid(MTOT / M_TILE, OUTF / N_TILE, KSPLIT);  // (4, 86, 4)
    l3b_gemm<<<grid, NTHREADS, SMEM_BYTES>>>(out);
}

// round 16
// speedup vs baseline: 1.0761x; 1.0761x over previous
#include <cuda_runtime.h>
#include <cuda_fp16.h>
#include <cuda_bf16.h>
#include <stdint.h>

// Problem constants
#define OUTF   11008
#define INF    4096
#define MTOT   512
#define NUM_GROUPS 1409024               // OUTF*INF/32
#define N8CNT  (OUTF / 8)                // 1376 n8 blocks
#define K16CNT (INF / 16)                // 256 k16 blocks

#define N_TILE 128
#define M_TILE 128
#define KCHUNK 64
#define KSPLIT 4
#define NCHUNK_JOB (INF / KCHUNK / KSPLIT)   // 16 chunks per job
#define NTHREADS 256                     // 8 warps, warp tile m64 x n32

#define PITCH 144                        // 128B data + 16B pad per row (conflict-free ldmatrix)
#define STAGE_BYTES (128 * PITCH)        // 18432 per A stage
#define SMEM_BYTES (3 * STAGE_BYTES)     // 55296 (A only, 3 stages)

// element counts for input identification (all distinct)
#define N_X   (MTOT * INF)               // 2,097,152 fp32
#define N_WQ  (NUM_GROUPS * 12)          // 16,908,288 int32 (ONE BYTE per int32)
#define N_WN  NUM_GROUPS                 // 1,409,024 (dtype auto-detected)
#define N_B   OUTF                       // 11,008 fp32

// prep kernel partition (512 threads per block): x convert + out init
#define NB_X   (MTOT * INF / 2 / 512)    // 2048
#define NB_OUT (MTOT * OUTF / 4 / 512)   // 2752

__device__ __align__(16) __half g_xh[MTOT * INF];                 // fp16 activations (4 MB)
__device__ __align__(16) uint32_t g_wf[(size_t)N8CNT * K16CNT * 64];  // fragment-native W (90 MB)

// ---------------- helpers ----------------
__device__ __forceinline__ uint32_t smem_u32(const void* p) {
    uint32_t a;
    asm("{ .reg .u64 t; cvta.to.shared.u64 t, %1; cvt.u32.u64 %0, t; }" : "=r"(a) : "l"(p));
    return a;
}

__device__ __forceinline__ void cpasync16(uint32_t dst, const void* src) {
    asm volatile("cp.async.cg.shared.global [%0], [%1], 16;" :: "r"(dst), "l"(src) : "memory");
}

__device__ __forceinline__ void ldm_x4(uint32_t* r, uint32_t addr) {
    asm volatile("ldmatrix.sync.aligned.m8n8.x4.shared.b16 {%0,%1,%2,%3}, [%4];"
                 : "=r"(r[0]), "=r"(r[1]), "=r"(r[2]), "=r"(r[3]) : "r"(addr));
}

__device__ __forceinline__ void mma16816(float* c, const uint32_t* a, const uint32_t b0, const uint32_t b1) {
    asm volatile(
        "mma.sync.aligned.m16n8k16.row.col.f32.f16.f16.f32 "
        "{%0,%1,%2,%3}, {%4,%5,%6,%7}, {%8,%9}, {%0,%1,%2,%3};"
        : "+f"(c[0]), "+f"(c[1]), "+f"(c[2]), "+f"(c[3])
        : "r"(a[0]), "r"(a[1]), "r"(a[2]), "r"(a[3]), "r"(b0), "r"(b1));
}

// Decode 8 3-bit codes from 3 bytes (each byte held in one int32), dequantize,
// pack to 4x half2 (even value in low half).
__device__ __forceinline__ uint4 dec8(int b0, int b1, int b2, float a, float nb) {
    float w0 = fmaf((float)(b0 & 7), a, nb);
    float w1 = fmaf((float)((b0 >> 3) & 7), a, nb);
    float w2 = fmaf((float)(((b0 >> 6) & 3) | ((b1 & 1) << 2)), a, nb);
    float w3 = fmaf((float)((b1 >> 1) & 7), a, nb);
    float w4 = fmaf((float)((b1 >> 4) & 7), a, nb);
    float w5 = fmaf((float)(((b1 >> 7) & 1) | ((b2 & 3) << 1)), a, nb);
    float w6 = fmaf((float)((b2 >> 2) & 7), a, nb);
    float w7 = fmaf((float)((b2 >> 5) & 7), a, nb);
    uint4 u;
    asm("cvt.rn.f16x2.f32 %0, %1, %2;" : "=r"(u.x) : "f"(w1), "f"(w0));
    asm("cvt.rn.f16x2.f32 %0, %1, %2;" : "=r"(u.y) : "f"(w3), "f"(w2));
    asm("cvt.rn.f16x2.f32 %0, %1, %2;" : "=r"(u.z) : "f"(w5), "f"(w4));
    asm("cvt.rn.f16x2.f32 %0, %1, %2;" : "=r"(u.w) : "f"(w7), "f"(w6));
    return u;
}

// ---------------- prep: x convert + out init ----------------
__global__ void __launch_bounds__(512) prep_kernel(
    const float* __restrict__ x, const float* __restrict__ bias, float* __restrict__ out)
{
    int b = blockIdx.x;
    if (b < NB_X) {
        int i = b * 512 + threadIdx.x;
        float2 v = ((const float2*)x)[i];
        ((__half2*)g_xh)[i] = __floats2half2_rn(v.x, v.y);
    } else {
        int i = (b - NB_X) * 512 + threadIdx.x;              // float4 index
        int n4 = (i % (OUTF / 4)) * 4;
        float4 bb = *(const float4*)(bias + n4);
        ((float4*)out)[i] = bb;
    }
}

// ---------------- dequant W into fragment-native layout ----------------
// Tile (nb, j): 64 uint32; uint32[l*2 + r] = half2( W[nb*8 + (l>>2)][j*16 + r*8 + (l&3)*2],
//                                                  W[same][.. + 1] )  -- exact m16n8k16 B frag.
// wq: ONE byte per int32; group g (32 values) = ints [g*12, g*12+12).
// Thread tid=j builds tile (nb, j) for all 8 rows; the 16 k-values of tile j are
// bytes [half*6, half*6+6) of group kg = j>>1, half = j&1.
__global__ void __launch_bounds__(256) dequant_frag_kernel(
    const void* __restrict__ wn, const int* __restrict__ wq)
{
    __shared__ int votes[3];
    const int nb = blockIdx.x;
    const int tid = threadIdx.x;

    if (tid < 3) votes[tid] = 0;
    __syncthreads();
    {   // dtype vote over wn[0..255] (norms lie in (0.01, 0.11))
        float a = ((const float*)wn)[tid];
        float h = __half2float(((const __half*)wn)[tid]);
        float c = __bfloat162float(((const __nv_bfloat16*)wn)[tid]);
        if (a > 0.009f && a < 0.115f) atomicAdd(&votes[0], 1);
        if (h > 0.009f && h < 0.115f) atomicAdd(&votes[1], 1);
        if (c > 0.009f && c < 0.115f) atomicAdd(&votes[2], 1);
    }
    __syncthreads();
    int mode = 1, best = votes[1];
    if (votes[0] > best) { best = votes[0]; mode = 0; }
    if (votes[2] > best) { best = votes[2]; mode = 2; }

    const int j = tid, kg = j >> 1, half = j & 1;
    uint4* dst = (uint4*)(g_wf + ((size_t)nb * K16CNT + j) * 64);
    #pragma unroll
    for (int r = 0; r < 8; r++) {
        const size_t gidx = ((size_t)(nb * 8 + r)) * (INF / 32) + kg;   // global group index
        const int2* p = (const int2*)(wq + gidx * 12 + half * 6);       // 6 ints = 6 bytes
        int2 p0 = __ldg(p), p1 = __ldg(p + 1), p2 = __ldg(p + 2);
        float n;
        if (mode == 0)      n = ((const float*)wn)[gidx];
        else if (mode == 1) n = __half2float(((const __half*)wn)[gidx]);
        else                n = __bfloat162float(((const __nv_bfloat16*)wn)[gidx]);
        float aa = n * (2.0f / 7.0f), nbv = -n;
        uint4 u = dec8(p0.x, p0.y, p1.x, aa, nbv);   // k 0..7  of this 16
        uint4 v = dec8(p1.y, p2.x, p2.y, aa, nbv);   // k 8..15 of this 16
        uint4 o0; o0.x = u.x; o0.y = v.x; o0.z = u.y; o0.w = v.y;   // lanes 4r,4r+1
        uint4 o1; o1.x = u.z; o1.y = v.z; o1.z = u.w; o1.w = v.w;   // lanes 4r+2,4r+3
        dst[r * 2]     = o0;
        dst[r * 2 + 1] = o1;
    }
}

// ---------------- pure fp16 GEMM: A via smem (R13 path), B via fragment LDG ----------------
__global__ void __launch_bounds__(NTHREADS, 2) l3b_gemm(float* __restrict__ out)
{
    extern __shared__ char smem[];
    const uint32_t sb = smem_u32(smem);
    const int tid = threadIdx.x;
    const int wid = tid >> 5, lid = tid & 31;
    const int wm = wid >> 2, wn_ = wid & 3;          // 2x4 warp grid, warp tile m64 x n32
    const int m0 = blockIdx.x * M_TILE;              // m fast-varying: L2 weight reuse
    const int n0 = blockIdx.y * N_TILE;
    const int c0 = blockIdx.z * NCHUNK_JOB;          // split-K chunk base

    const uint32_t As0 = sb;                         // 3 A stages

    // A cp.async mapping (identical to R13's A half)
    const int ld_row = tid >> 3, ld_col = tid & 7;
    const uint32_t ld_soff = (uint32_t)(ld_row * PITCH + ld_col * 16);
    const __half* ag = g_xh + (size_t)(m0 + ld_row) * INF + ld_col * 8;

    // A ldmatrix lane base (identical to R13)
    const uint32_t a_loff = (uint32_t)((wm * 64 + (lid & 15)) * PITCH + ((lid >> 4) * 8) * 2);

    // B fragment LDG base: warp covers n8 blocks [n0/8 + wn_*4, +4)
    const uint2* bptr = (const uint2*)g_wf + ((size_t)((n0 >> 3) + wn_ * 4) * K16CNT) * 32 + lid;
    // tile t offset: t * K16CNT * 32 uint2; k16 j offset: j * 32 uint2

    float acc[4][4][4];
    #pragma unroll
    for (int mt = 0; mt < 4; mt++)
        #pragma unroll
        for (int nt = 0; nt < 4; nt++)
            #pragma unroll
            for (int e = 0; e < 4; e++) acc[mt][nt][e] = 0.0f;

    uint2 bf[2][4];
    // issue B fragments for chunk c0, k-step 0 immediately (no smem dependency)
    {
        const int j0 = c0 * 4;
        #pragma unroll
        for (int t = 0; t < 4; t++)
            bf[0][t] = __ldg(bptr + (size_t)t * (K16CNT * 32) + (size_t)j0 * 32);
    }

    // ---- prologue: stage A chunks c0 -> stage0, c0+1 -> stage1 ----
    #pragma unroll
    for (int s = 0; s < 2; s++) {
        const uint32_t As = As0 + (uint32_t)s * STAGE_BYTES;
        const int koff = (c0 + s) * KCHUNK;
        #pragma unroll
        for (int p = 0; p < 4; p++)
            cpasync16(As + ld_soff + (uint32_t)(p * 32 * PITCH), ag + (size_t)(p * 32) * INF + koff);
        asm volatile("cp.async.commit_group;" ::: "memory");
    }
    asm volatile("cp.async.wait_group 1;" ::: "memory");   // A(c0) landed
    __syncthreads();

    uint32_t af[2][4][4];
    #pragma unroll
    for (int mt = 0; mt < 4; mt++)
        ldm_x4(af[0][mt], As0 + a_loff + (uint32_t)(mt * 16 * PITCH));

    int rd3 = 0;                                     // A read stage (i % 3)

    #pragma unroll 1
    for (int i = 0; i < NCHUNK_JOB; i++) {
        const uint32_t As = As0 + (uint32_t)rd3 * STAGE_BYTES;
        const bool more = (i + 1 < NCHUNK_JOB);
        const bool more2 = (i + 2 < NCHUNK_JOB);

        // ---- issue A chunk i+2 cp.async into stage (rd3+2)%3 ----
        if (more2) {
            int wr3 = rd3 + 2; if (wr3 >= 3) wr3 -= 3;
            const uint32_t Aw = As0 + (uint32_t)wr3 * STAGE_BYTES;
            const int koff = (c0 + i + 2) * KCHUNK;
            #pragma unroll
            for (int p = 0; p < 4; p++)
                cpasync16(Aw + ld_soff + (uint32_t)(p * 32 * PITCH), ag + (size_t)(p * 32) * INF + koff);
            asm volatile("cp.async.commit_group;" ::: "memory");
        }

        // ---- compute chunk i: 4 k16 steps; af + bf double-buffered ----
        #pragma unroll
        for (int ks = 0; ks < 4; ks++) {
            const int cur = ks & 1;
            if (ks < 3) {
                // B fragments for k-step ks+1 (LDG, longest latency: issue first)
                const int j = (c0 + i) * 4 + ks + 1;
                #pragma unroll
                for (int t = 0; t < 4; t++)
                    bf[cur ^ 1][t] = __ldg(bptr + (size_t)t * (K16CNT * 32) + (size_t)j * 32);
                // A fragments for k-step ks+1
                #pragma unroll
                for (int mt = 0; mt < 4; mt++)
                    ldm_x4(af[cur ^ 1][mt], As + a_loff + (uint32_t)(mt * 16 * PITCH + (ks + 1) * 32));
            } else if (more) {
                // B fragments for next chunk's k-step 0 (no barrier needed: B is global)
                const int j = (c0 + i + 1) * 4;
                #pragma unroll
                for (int t = 0; t < 4; t++)
                    bf[0][t] = __ldg(bptr + (size_t)t * (K16CNT * 32) + (size_t)j * 32);
            }
            // 16 MMAs of k-step ks
            #pragma unroll
            for (int mt = 0; mt < 4; mt++)
                #pragma unroll
                for (int nt = 0; nt < 4; nt++)
                    mma16816(acc[mt][nt], af[cur][mt], bf[cur][nt].x, bf[cur][nt].y);
        }

        // ---- A stage rotation: ensure chunk i+1 landed; preload its ks0 A frags ----
        if (more) {
            if (more2) { asm volatile("cp.async.wait_group 1;" ::: "memory"); }
            else       { asm volatile("cp.async.wait_group 0;" ::: "memory"); }
            __syncthreads();
            int rdn = rd3 + 1; if (rdn >= 3) rdn -= 3;
            const uint32_t An = As0 + (uint32_t)rdn * STAGE_BYTES;
            #pragma unroll
            for (int mt = 0; mt < 4; mt++)
                ldm_x4(af[0][mt], An + a_loff + (uint32_t)(mt * 16 * PITCH));
        }

        rd3++; if (rd3 == 3) rd3 = 0;
    }

    // ---- epilogue: atomic accumulate split-K partials (bias pre-broadcast by prep) ----
    #pragma unroll
    for (int mt = 0; mt < 4; mt++) {
        #pragma unroll
        for (int nt = 0; nt < 4; nt++) {
            int m = m0 + wm * 64 + mt * 16 + (lid >> 2);
            int nl = n0 + wn_ * 32 + nt * 8 + (lid & 3) * 2;
            float* p0 = out + (size_t)m * OUTF + nl;
            float* p1 = out + (size_t)(m + 8) * OUTF + nl;
            atomicAdd(p0,     acc[mt][nt][0]);
            atomicAdd(p0 + 1, acc[mt][nt][1]);
            atomicAdd(p1,     acc[mt][nt][2]);
            atomicAdd(p1 + 1, acc[mt][nt][3]);
        }
    }
}

// ---------------- launch ----------------
extern "C" void kernel_launch(void* const* d_in, const int* in_sizes, int n_in,
                              void* d_out, int out_size) {
    // Bind inputs by element count (robust to metadata ordering).
    const float* x    = 0;
    const int*   wq   = 0;
    const void*  wn   = 0;
    const float* bias = 0;
    for (int i = 0; i < n_in; i++) {
        switch (in_sizes[i]) {
            case N_X:  x    = (const float*)d_in[i]; break;
            case N_WQ: wq   = (const int*)d_in[i];   break;
            case N_WN: wn   = d_in[i];               break;
            case N_B:  bias = (const float*)d_in[i]; break;
            default: break;
        }
    }
    if (!x)    x    = (const float*)d_in[0];
    if (!wq)   wq   = (const int*)d_in[1];
    if (!wn)   wn   = d_in[2];
    if (!bias) bias = (const float*)d_in[3];

    float* out = (float*)d_out;

    cudaFuncSetAttribute(l3b_gemm, cudaFuncAttributeMaxDynamicSharedMemorySize, SMEM_BYTES);

    prep_kernel<<<NB_X + NB_OUT, 512>>>(x, bias, out);
    dequant_frag_kernel<<<N8CNT, 256>>>(wn, wq);

    dim3 grid(MTOT / M_TILE, OUTF / N_TILE, KSPLIT);  // (4, 86, 4)
    l3b_gemm<<<grid, NTHREADS, SMEM_BYTES>>>(out);
}

// round 17
// speedup vs baseline: 1.2874x; 1.1964x over previous
#include <cuda_runtime.h>
#include <cuda_fp16.h>
#include <cuda_bf16.h>
#include <stdint.h>

// Problem constants
#define OUTF   11008
#define INF    4096
#define MTOT   512
#define NUM_GROUPS 1409024               // OUTF*INF/32

#define N_TILE 128
#define M_TILE 128
#define KCHUNK 64
#define KSPLIT 4
#define NCHUNK_JOB (INF / KCHUNK / KSPLIT)   // 16 chunks per job
#define NTHREADS 128                     // 4 warps, warp tile m64 x n64 (pure GEMM, no spills)

#define PITCH 144                        // 128B data + 16B pad per row (conflict-free ldmatrix)
#define STAGE_BYTES (128 * PITCH)        // 18432 per tile (A or B)
// A: 3 stages + B: 3 stages
#define SMEM_BYTES (6 * STAGE_BYTES)     // 110592 -> 2 CTAs/SM (221KB of 228KB)

// element counts for input identification (all distinct)
#define N_X   (MTOT * INF)               // 2,097,152 fp32
#define N_WQ  (NUM_GROUPS * 12)          // 16,908,288 int32 (ONE BYTE per int32)
#define N_WN  NUM_GROUPS                 // 1,409,024 (dtype auto-detected)
#define N_B   OUTF                       // 11,008 fp32

// fused prep partition (512 threads per block)
#define NB_DQ  (NUM_GROUPS / 512)        // 2752  (dequant: 1 group/thread)
#define NB_X   (MTOT * INF / 2 / 512)    // 2048  (x convert: 1 half2/thread)
#define NB_OUT (MTOT * OUTF / 4 / 512)   // 2752  (out init: 1 float4/thread)

__device__ __align__(16) __half g_xh[MTOT * INF];     // fp16 activations (4 MB)
__device__ __align__(16) __half g_w[(size_t)OUTF * INF];  // dequantized weights (90 MB)

// ---------------- helpers ----------------
__device__ __forceinline__ uint32_t smem_u32(const void* p) {
    uint32_t a;
    asm("{ .reg .u64 t; cvta.to.shared.u64 t, %1; cvt.u32.u64 %0, t; }" : "=r"(a) : "l"(p));
    return a;
}

__device__ __forceinline__ void cpasync16(uint32_t dst, const void* src) {
    asm volatile("cp.async.cg.shared.global [%0], [%1], 16;" :: "r"(dst), "l"(src) : "memory");
}

__device__ __forceinline__ void ldm_x4(uint32_t* r, uint32_t addr) {
    asm volatile("ldmatrix.sync.aligned.m8n8.x4.shared.b16 {%0,%1,%2,%3}, [%4];"
                 : "=r"(r[0]), "=r"(r[1]), "=r"(r[2]), "=r"(r[3]) : "r"(addr));
}

__device__ __forceinline__ void mma16816(float* c, const uint32_t* a, const uint32_t b0, const uint32_t b1) {
    asm volatile(
        "mma.sync.aligned.m16n8k16.row.col.f32.f16.f16.f32 "
        "{%0,%1,%2,%3}, {%4,%5,%6,%7}, {%8,%9}, {%0,%1,%2,%3};"
        : "+f"(c[0]), "+f"(c[1]), "+f"(c[2]), "+f"(c[3])
        : "r"(a[0]), "r"(a[1]), "r"(a[2]), "r"(a[3]), "r"(b0), "r"(b1));
}

// Decode 8 3-bit codes from 3 bytes (each byte held in one int32), dequantize,
// pack to 4x half2 (even value in low half).
__device__ __forceinline__ uint4 dec8(int b0, int b1, int b2, float a, float nb) {
    float w0 = fmaf((float)(b0 & 7), a, nb);
    float w1 = fmaf((float)((b0 >> 3) & 7), a, nb);
    float w2 = fmaf((float)(((b0 >> 6) & 3) | ((b1 & 1) << 2)), a, nb);
    float w3 = fmaf((float)((b1 >> 1) & 7), a, nb);
    float w4 = fmaf((float)((b1 >> 4) & 7), a, nb);
    float w5 = fmaf((float)(((b1 >> 7) & 1) | ((b2 & 3) << 1)), a, nb);
    float w6 = fmaf((float)((b2 >> 2) & 7), a, nb);
    float w7 = fmaf((float)((b2 >> 5) & 7), a, nb);
    uint4 u;
    asm("cvt.rn.f16x2.f32 %0, %1, %2;" : "=r"(u.x) : "f"(w1), "f"(w0));
    asm("cvt.rn.f16x2.f32 %0, %1, %2;" : "=r"(u.y) : "f"(w3), "f"(w2));
    asm("cvt.rn.f16x2.f32 %0, %1, %2;" : "=r"(u.z) : "f"(w5), "f"(w4));
    asm("cvt.rn.f16x2.f32 %0, %1, %2;" : "=r"(u.w) : "f"(w7), "f"(w6));
    return u;
}

// ---------------- fused prep: W dequant (with local wn-dtype vote), x convert, out init ----
// Norms lie in (0.01, 0.11); dequant blocks re-vote dtype locally over wn[0..255].
__global__ void __launch_bounds__(512) prep_kernel(
    const void* __restrict__ wn, const int* __restrict__ wq,
    const float* __restrict__ x, const float* __restrict__ bias,
    float* __restrict__ out)
{
    int b = blockIdx.x;
    if (b < NB_DQ) {
        __shared__ int votes[3];
        if (threadIdx.x < 3) votes[threadIdx.x] = 0;
        __syncthreads();
        {
            int j = threadIdx.x & 255;
            float a = ((const float*)wn)[j];
            float h = __half2float(((const __half*)wn)[j]);
            float c = __bfloat162float(((const __nv_bfloat16*)wn)[j]);
            if (a > 0.009f && a < 0.115f) atomicAdd(&votes[0], 1);
            if (h > 0.009f && h < 0.115f) atomicAdd(&votes[1], 1);
            if (c > 0.009f && c < 0.115f) atomicAdd(&votes[2], 1);
        }
        __syncthreads();
        int mode = 1, best = votes[1];
        if (votes[0] > best) { best = votes[0]; mode = 0; }
        if (votes[2] > best) { best = votes[2]; mode = 2; }

        int g = b * 512 + threadIdx.x;               // group index (contiguous in k)
        float n;
        if (mode == 0)      n = ((const float*)wn)[g];
        else if (mode == 1) n = __half2float(((const __half*)wn)[g]);
        else                n = __bfloat162float(((const __nv_bfloat16*)wn)[g]);
        const int4* pk = (const int4*)wq + (size_t)g * 3;
        int4 w0 = __ldg(pk), w1 = __ldg(pk + 1), w2 = __ldg(pk + 2);
        float aa = n * (2.0f / 7.0f), nb = -n;
        uint4* dst = (uint4*)(g_w + (size_t)g * 32);  // 32 halves = 4 x uint4
        dst[0] = dec8(w0.x, w0.y, w0.z, aa, nb);
        dst[1] = dec8(w0.w, w1.x, w1.y, aa, nb);
        dst[2] = dec8(w1.z, w1.w, w2.x, aa, nb);
        dst[3] = dec8(w2.y, w2.z, w2.w, aa, nb);
    } else if (b < NB_DQ + NB_X) {
        int i = (b - NB_DQ) * 512 + threadIdx.x;
        float2 v = ((const float2*)x)[i];
        ((__half2*)g_xh)[i] = __floats2half2_rn(v.x, v.y);
    } else {
        int i = (b - NB_DQ - NB_X) * 512 + threadIdx.x;     // float4 index
        int n4 = (i % (OUTF / 4)) * 4;
        float4 bb = *(const float4*)(bias + n4);
        ((float4*)out)[i] = bb;
    }
}

// ---------------- pure fp16 GEMM, split-K, 4 warps @ m64n64, 3-stage A+B cp.async ----------------
__global__ void __launch_bounds__(NTHREADS, 2) l3b_gemm(float* __restrict__ out)
{
    extern __shared__ char smem[];
    const uint32_t sb = smem_u32(smem);
    const int tid = threadIdx.x;
    const int wid = tid >> 5, lid = tid & 31;
    const int wm = wid >> 1, wn_ = wid & 1;          // 2x2 warp grid, warp tile m64 x n64
    const int m0 = blockIdx.x * M_TILE;              // m fast-varying: L2 weight reuse
    const int n0 = blockIdx.y * N_TILE;
    const int c0 = blockIdx.z * NCHUNK_JOB;          // split-K chunk base

    const uint32_t As0 = sb;                         // 3 A stages
    const uint32_t Bs0 = sb + 3 * STAGE_BYTES;       // 3 B stages

    // cp.async per-thread mapping: 8 x 16B each for A and B (128 rows x 8 cols of uint4)
    const int ld_row = tid >> 3, ld_col = tid & 7;   // base row 0..15 (step 16 per p), col 0..7
    const uint32_t ld_soff = (uint32_t)(ld_row * PITCH + ld_col * 16);
    const __half* ag = g_xh + (size_t)(m0 + ld_row) * INF + ld_col * 8;
    const __half* bg = g_w  + (size_t)(n0 + ld_row) * INF + ld_col * 8;

    // ldmatrix lane base offsets (within a stage)
    const uint32_t a_loff = (uint32_t)((wm * 64 + (lid & 15)) * PITCH + ((lid >> 4) * 8) * 2);
    const uint32_t b_loff = (uint32_t)((wn_ * 64 + ((lid >> 4) << 3) + (lid & 7)) * PITCH
                                       + (((lid >> 3) & 1) * 8) * 2);

    float acc[4][8][4];
    #pragma unroll
    for (int mt = 0; mt < 4; mt++)
        #pragma unroll
        for (int nt = 0; nt < 8; nt++)
            #pragma unroll
            for (int e = 0; e < 4; e++) acc[mt][nt][e] = 0.0f;

    // ---- prologue: stage chunks c0 -> stage0, c0+1 -> stage1 (A and B per group) ----
    #pragma unroll
    for (int s = 0; s < 2; s++) {
        const uint32_t As = As0 + (uint32_t)s * STAGE_BYTES;
        const uint32_t Bs = Bs0 + (uint32_t)s * STAGE_BYTES;
        const int koff = (c0 + s) * KCHUNK;
        #pragma unroll
        for (int p = 0; p < 8; p++) {
            cpasync16(As + ld_soff + (uint32_t)(p * 16 * PITCH), ag + (size_t)(p * 16) * INF + koff);
            cpasync16(Bs + ld_soff + (uint32_t)(p * 16 * PITCH), bg + (size_t)(p * 16) * INF + koff);
        }
        asm volatile("cp.async.commit_group;" ::: "memory");
    }
    asm volatile("cp.async.wait_group 1;" ::: "memory");   // chunk c0 landed
    __syncthreads();

    int rd3 = 0;                                     // read stage (i % 3)

    #pragma unroll 1
    for (int i = 0; i < NCHUNK_JOB; i++) {
        const uint32_t As = As0 + (uint32_t)rd3 * STAGE_BYTES;
        const uint32_t Bs = Bs0 + (uint32_t)rd3 * STAGE_BYTES;

        const bool more = (i + 1 < NCHUNK_JOB);
        const bool more2 = (i + 2 < NCHUNK_JOB);

        // ---- issue chunk i+2 cp.async into stage (rd3+2)%3 ----
        if (more2) {
            int wr3 = rd3 + 2; if (wr3 >= 3) wr3 -= 3;
            const uint32_t Aw = As0 + (uint32_t)wr3 * STAGE_BYTES;
            const uint32_t Bw = Bs0 + (uint32_t)wr3 * STAGE_BYTES;
            const int koff = (c0 + i + 2) * KCHUNK;
            #pragma unroll
            for (int p = 0; p < 8; p++) {
                cpasync16(Aw + ld_soff + (uint32_t)(p * 16 * PITCH), ag + (size_t)(p * 16) * INF + koff);
                cpasync16(Bw + ld_soff + (uint32_t)(p * 16 * PITCH), bg + (size_t)(p * 16) * INF + koff);
            }
            asm volatile("cp.async.commit_group;" ::: "memory");
        }

        // ---- compute chunk i: 4 k16 steps; af double-buffered (R13 pattern, widened to n64) ----
        {
            uint32_t af[2][4][4], bf[2][4][4];
            // preload k-step 0
            #pragma unroll
            for (int mt = 0; mt < 4; mt++)
                ldm_x4(af[0][mt], As + a_loff + (uint32_t)(mt * 16 * PITCH));
            #pragma unroll
            for (int nt2 = 0; nt2 < 4; nt2++)
                ldm_x4(bf[0][nt2], Bs + b_loff + (uint32_t)(nt2 * 16 * PITCH));

            #pragma unroll
            for (int ks = 0; ks < 4; ks++) {
                const int cur = ks & 1, nxt = cur ^ 1;
                // prefetch A fragments of k-step ks+1 (overlaps with MMAs below)
                if (ks < 3) {
                    #pragma unroll
                    for (int mt = 0; mt < 4; mt++)
                        ldm_x4(af[nxt][mt], As + a_loff + (uint32_t)(mt * 16 * PITCH + (ks + 1) * 32));
                }
                // 32 MMAs of k-step ks
                #pragma unroll
                for (int mt = 0; mt < 4; mt++)
                    #pragma unroll
                    for (int nt = 0; nt < 8; nt++)
                        mma16816(acc[mt][nt], af[cur][mt],
                                 bf[cur][nt >> 1][(nt & 1) * 2], bf[cur][nt >> 1][(nt & 1) * 2 + 1]);
                // B fragments of k-step ks+1 (after last use of bf[cur])
                if (ks < 3) {
                    #pragma unroll
                    for (int nt2 = 0; nt2 < 4; nt2++)
                        ldm_x4(bf[nxt][nt2], Bs + b_loff + (uint32_t)(nt2 * 16 * PITCH + (ks + 1) * 32));
                }
            }
        }

        // ---- ensure chunk i+1 landed; sync stage rotation ----
        if (more) {
            if (more2) { asm volatile("cp.async.wait_group 1;" ::: "memory"); }
            else       { asm volatile("cp.async.wait_group 0;" ::: "memory"); }
            __syncthreads();
        }

        rd3++; if (rd3 == 3) rd3 = 0;
    }

    // ---- epilogue: atomic accumulate split-K partials (bias pre-broadcast by prep) ----
    #pragma unroll
    for (int mt = 0; mt < 4; mt++) {
        #pragma unroll
        for (int nt = 0; nt < 8; nt++) {
            int m = m0 + wm * 64 + mt * 16 + (lid >> 2);
            int nl = n0 + wn_ * 64 + nt * 8 + (lid & 3) * 2;
            float* p0 = out + (size_t)m * OUTF + nl;
            float* p1 = out + (size_t)(m + 8) * OUTF + nl;
            atomicAdd(p0,     acc[mt][nt][0]);
            atomicAdd(p0 + 1, acc[mt][nt][1]);
            atomicAdd(p1,     acc[mt][nt][2]);
            atomicAdd(p1 + 1, acc[mt][nt][3]);
        }
    }
}

// ---------------- launch ----------------
extern "C" void kernel_launch(void* const* d_in, const int* in_sizes, int n_in,
                              void* d_out, int out_size) {
    // Bind inputs by element count (robust to metadata ordering).
    const float* x    = 0;
    const int*   wq   = 0;
    const void*  wn   = 0;
    const float* bias = 0;
    for (int i = 0; i < n_in; i++) {
        switch (in_sizes[i]) {
            case N_X:  x    = (const float*)d_in[i]; break;
            case N_WQ: wq   = (const int*)d_in[i];   break;
            case N_WN: wn   = d_in[i];               break;
            case N_B:  bias = (const float*)d_in[i]; break;
            default: break;
        }
    }
    if (!x)    x    = (const float*)d_in[0];
    if (!wq)   wq   = (const int*)d_in[1];
    if (!wn)   wn   = d_in[2];
    if (!bias) bias = (const float*)d_in[3];

    float* out = (float*)d_out;

    cudaFuncSetAttribute(l3b_gemm, cudaFuncAttributeMaxDynamicSharedMemorySize, SMEM_BYTES);

    prep_kernel<<<NB_DQ + NB_X + NB_OUT, 512>>>(wn, wq, x, bias, out);

    dim3 grid(MTOT / M_TILE, OUTF / N_TILE, KSPLIT);  // (4, 86, 4)
    l3b_gemm<<<grid, NTHREADS, SMEM_BYTES>>>(out);
}